// round 15
// baseline (speedup 1.0000x reference)
#include <cuda_runtime.h>
#include <math.h>
#include <mma.h>
using namespace nvcuda;

#define BB 32
#define SS 96
#define TN 96
#define EE 256
#define HH 512
#define H4 2048
#define H2 1024
#define VV 32000

// ---------------- static scratch (no allocations) ----------------
__device__ float d_xsrc[BB*SS*EE];
__device__ float d_ytrg[BB*TN*EE];
__device__ float d_xpf[BB*SS*H4];
__device__ float d_xpb[BB*SS*H4];
__device__ float d_x1[BB*SS*H2];
__device__ float d_x2[BB*SS*H2];
__device__ float d_enc[BB*SS*HH];
__device__ float d_y1[BB*TN*HH];
__device__ float d_y2[BB*TN*HH];
__device__ float d_comb[BB*TN*H2];
__device__ float d_ecT0[BB*H2];
__device__ float d_ecT1[BB*H2];
__device__ float d_ehT0[BB*H2];
__device__ float d_ehT1[BB*H2];
__device__ float d_dh0[BB*HH];
__device__ float d_dh1[BB*HH];
__device__ float d_dc0[BB*HH];
__device__ float d_dc1[BB*HH];

// per-block step flags, padded to one per 128B cache line; [ (dir*64+jblk) * 32 ]
#define FSTRIDE 32
__device__ unsigned d_flag[128*FSTRIDE];

__global__ void flag_reset_kernel() {
    int i = blockIdx.x * blockDim.x + threadIdx.x;
    if (i < 128*FSTRIDE) d_flag[i] = 0u;
}

__device__ __forceinline__ unsigned ld_acq(const unsigned* p) {
    unsigned v;
    asm volatile("ld.global.acquire.gpu.b32 %0, [%1];" : "=r"(v) : "l"(p) : "memory");
    return v;
}
__device__ __forceinline__ void st_rel(unsigned* p, unsigned v) {
    asm volatile("st.global.release.gpu.b32 [%0], %1;" :: "l"(p), "r"(v) : "memory");
}

// ---------------- helpers ----------------
__global__ void embed_kernel(float* __restrict__ out, const float* __restrict__ emb,
                             const int* __restrict__ seq, int n) {
    int i = blockIdx.x * blockDim.x + threadIdx.x;
    if (i < n) {
        int tok = seq[i >> 8];
        out[i] = emb[(size_t)tok * EE + (i & 255)];
    }
}

__device__ __forceinline__ float fast_sigmoid(float x) {
    return 1.f / (1.f + __expf(-x));
}
__device__ __forceinline__ float fast_tanh(float x) {
    return 2.f / (1.f + __expf(-2.f * x)) - 1.f;
}

// ---------------- fused 4x small projection (M=32, N=512, K=1024) ----------------
__global__ __launch_bounds__(256) void proj4_kernel(
    const float* __restrict__ A0, const float* __restrict__ A1,
    const float* __restrict__ A2, const float* __restrict__ A3,
    const float* __restrict__ hpW, const float* __restrict__ hpb,
    const float* __restrict__ cpW, const float* __restrict__ cpb,
    float* __restrict__ C0, float* __restrict__ C1,
    float* __restrict__ C2, float* __restrict__ C3)
{
    const float* A; const float* W; const float* bias; float* C;
    switch (blockIdx.z) {
        case 0: A = A0; W = hpW;            bias = hpb;      C = C0; break;
        case 1: A = A1; W = hpW + HH*H2;    bias = hpb + HH; C = C1; break;
        case 2: A = A2; W = cpW;            bias = cpb;      C = C2; break;
        default:A = A3; W = cpW + HH*H2;    bias = cpb + HH; C = C3; break;
    }
    const int M = BB, N = HH, K = H2;

    __shared__ float As[16][132];
    __shared__ float Ws[16][132];
    const int bn = blockIdx.x * 128;
    const int tid = threadIdx.x;
    const int trow = (tid >> 4) * 8;
    const int tcol = (tid & 15) * 8;

    float acc[8][8];
#pragma unroll
    for (int i = 0; i < 8; i++)
#pragma unroll
        for (int j = 0; j < 8; j++) acc[i][j] = 0.f;

    for (int k0 = 0; k0 < K; k0 += 16) {
#pragma unroll
        for (int i = 0; i < 2; i++) {
            int q = tid + i * 256;
            int r = q >> 2;
            int c = (q & 3) * 4;
            float4 v = make_float4(0.f, 0.f, 0.f, 0.f);
            if (r < M) v = *(const float4*)(A + (size_t)r * K + k0 + c);
            As[c + 0][r] = v.x; As[c + 1][r] = v.y; As[c + 2][r] = v.z; As[c + 3][r] = v.w;
            float4 u = *(const float4*)(W + (size_t)(bn + r) * K + k0 + c);
            Ws[c + 0][r] = u.x; Ws[c + 1][r] = u.y; Ws[c + 2][r] = u.z; Ws[c + 3][r] = u.w;
        }
        __syncthreads();
#pragma unroll
        for (int kk = 0; kk < 16; kk++) {
            float4 a0 = *(const float4*)&As[kk][trow];
            float4 a1 = *(const float4*)&As[kk][trow + 4];
            float4 b0 = *(const float4*)&Ws[kk][tcol];
            float4 b1 = *(const float4*)&Ws[kk][tcol + 4];
            float av[8] = {a0.x, a0.y, a0.z, a0.w, a1.x, a1.y, a1.z, a1.w};
            float bv[8] = {b0.x, b0.y, b0.z, b0.w, b1.x, b1.y, b1.z, b1.w};
#pragma unroll
            for (int i = 0; i < 8; i++)
#pragma unroll
                for (int j = 0; j < 8; j++) acc[i][j] += av[i] * bv[j];
        }
        __syncthreads();
    }

    float bb[8];
#pragma unroll
    for (int j = 0; j < 8; j++) bb[j] = bias[bn + tcol + j];
#pragma unroll
    for (int i = 0; i < 8; i++) {
        int r = trow + i;
        if (r < M) {
            float* cp = C + (size_t)r * N + bn + tcol;
#pragma unroll
            for (int j = 0; j < 8; j += 4) {
                float4 v;
                v.x = acc[i][j + 0] + bb[j + 0];
                v.y = acc[i][j + 1] + bb[j + 1];
                v.z = acc[i][j + 2] + bb[j + 2];
                v.w = acc[i][j + 3] + bb[j + 3];
                *(float4*)(cp + j) = v;
            }
        }
    }
}

// ---------------- TF32 tensor-core GEMM (FC + big projections) ----------------
__global__ __launch_bounds__(256) void gemm_tf32(
    const float* __restrict__ A, const float* __restrict__ W,
    const float* __restrict__ bias, float* __restrict__ C,
    int M, int N, int K)
{
    extern __shared__ float sm[];
    float* Ab[2] = { sm,          sm + 5120 };
    float* Bb[2] = { sm + 10240,  sm + 15360 };

    const int bm = blockIdx.x * 128;
    const int bn = blockIdx.y * 128;
    const int tid  = threadIdx.x;
    const int warp = tid >> 5;
    const int lane = tid & 31;
    const int wm = warp & 3;
    const int wn = warp >> 2;

    wmma::fragment<wmma::accumulator, 16, 16, 8, float> c[2][4];
#pragma unroll
    for (int i = 0; i < 2; i++)
#pragma unroll
        for (int j = 0; j < 4; j++) wmma::fill_fragment(c[i][j], 0.f);

    const int lr = tid >> 1;
    const int lc = (tid & 1) * 16;
    const float* ap = A + (size_t)(bm + lr) * K + lc;
    const float* wp = W + (size_t)(bn + lr) * K + lc;

    float4 ra[4], rw[4];
#pragma unroll
    for (int q = 0; q < 4; q++) {
        ra[q] = *(const float4*)(ap + q * 4);
        rw[q] = *(const float4*)(wp + q * 4);
    }
    {
        float* ad = Ab[0] + lr * 40 + lc;
        float* bd = Bb[0] + lr * 40 + lc;
#pragma unroll
        for (int q = 0; q < 4; q++) {
            ad[q*4+0] = wmma::__float_to_tf32(ra[q].x);
            ad[q*4+1] = wmma::__float_to_tf32(ra[q].y);
            ad[q*4+2] = wmma::__float_to_tf32(ra[q].z);
            ad[q*4+3] = wmma::__float_to_tf32(ra[q].w);
            bd[q*4+0] = wmma::__float_to_tf32(rw[q].x);
            bd[q*4+1] = wmma::__float_to_tf32(rw[q].y);
            bd[q*4+2] = wmma::__float_to_tf32(rw[q].z);
            bd[q*4+3] = wmma::__float_to_tf32(rw[q].w);
        }
    }
    __syncthreads();

    const int ksteps = K >> 5;
    int cur = 0;
    for (int ks = 0; ks < ksteps; ks++) {
        const bool more = (ks + 1 < ksteps);
        if (more) {
            const float* a2 = ap + (ks + 1) * 32;
            const float* w2 = wp + (ks + 1) * 32;
#pragma unroll
            for (int q = 0; q < 4; q++) {
                ra[q] = *(const float4*)(a2 + q * 4);
                rw[q] = *(const float4*)(w2 + q * 4);
            }
        }
        const float* As = Ab[cur];
        const float* Bs = Bb[cur];
#pragma unroll
        for (int kk = 0; kk < 4; kk++) {
            wmma::fragment<wmma::matrix_a, 16, 16, 8, wmma::precision::tf32, wmma::row_major> a[2];
            wmma::fragment<wmma::matrix_b, 16, 16, 8, wmma::precision::tf32, wmma::col_major> b[4];
#pragma unroll
            for (int i = 0; i < 2; i++)
                wmma::load_matrix_sync(a[i], As + (wm * 32 + i * 16) * 40 + kk * 8, 40);
#pragma unroll
            for (int j = 0; j < 4; j++)
                wmma::load_matrix_sync(b[j], Bs + (wn * 64 + j * 16) * 40 + kk * 8, 40);
#pragma unroll
            for (int i = 0; i < 2; i++)
#pragma unroll
                for (int j = 0; j < 4; j++)
                    wmma::mma_sync(c[i][j], a[i], b[j], c[i][j]);
        }
        if (more) {
            float* ad = Ab[cur ^ 1] + lr * 40 + lc;
            float* bd = Bb[cur ^ 1] + lr * 40 + lc;
#pragma unroll
            for (int q = 0; q < 4; q++) {
                ad[q*4+0] = wmma::__float_to_tf32(ra[q].x);
                ad[q*4+1] = wmma::__float_to_tf32(ra[q].y);
                ad[q*4+2] = wmma::__float_to_tf32(ra[q].z);
                ad[q*4+3] = wmma::__float_to_tf32(ra[q].w);
                bd[q*4+0] = wmma::__float_to_tf32(rw[q].x);
                bd[q*4+1] = wmma::__float_to_tf32(rw[q].y);
                bd[q*4+2] = wmma::__float_to_tf32(rw[q].z);
                bd[q*4+3] = wmma::__float_to_tf32(rw[q].w);
            }
            __syncthreads();
            cur ^= 1;
        }
    }
    __syncthreads();

    float* wbuf = sm + warp * 320;
    const int er = lane >> 1;
    const int ec = (lane & 1) * 8;
#pragma unroll
    for (int i = 0; i < 2; i++) {
#pragma unroll
        for (int j = 0; j < 4; j++) {
            wmma::store_matrix_sync(wbuf, c[i][j], 20, wmma::mem_row_major);
            __syncwarp();
            const int gr = bm + wm * 32 + i * 16 + er;
            const int gc = bn + wn * 64 + j * 16 + ec;
            const float* bp = bias + gc;
            float* dst = C + (size_t)gr * N + gc;
            float4 v0, v1;
            v0.x = wbuf[er * 20 + ec + 0] + bp[0];
            v0.y = wbuf[er * 20 + ec + 1] + bp[1];
            v0.z = wbuf[er * 20 + ec + 2] + bp[2];
            v0.w = wbuf[er * 20 + ec + 3] + bp[3];
            v1.x = wbuf[er * 20 + ec + 4] + bp[4];
            v1.y = wbuf[er * 20 + ec + 5] + bp[5];
            v1.z = wbuf[er * 20 + ec + 6] + bp[6];
            v1.w = wbuf[er * 20 + ec + 7] + bp[7];
            *(float4*)(dst)     = v0;
            *(float4*)(dst + 4) = v1;
            __syncwarp();
        }
    }
}

// ---------------- persistent LSTM scan: tensor-core gemv ----------------
// Per block (256 thr, 8 warps): D[32 batch x 32 gaterow] = h[32x512] @ Uslice^T.
// U_hi fragments preloaded in registers. h staged hi/lo (exact h x tf32 U).
// Inter-block sync: line-padded per-block flags, release-store / acquire-load,
// nanosleep poll backoff.
#define HPAD 520
#define RPAD 36
#define RWARP (32*RPAD)
#define XSM_F (4*8*33)
#define SCAN_SMEM ((2*32*HPAD + 8*RWARP + XSM_F) * 4)

__device__ __forceinline__ void scan_mma(
    const float* __restrict__ xp,   // [B][96][2048] for this dir
    const float* __restrict__ U,    // [2048][512]
    const float* __restrict__ h0,   // [B][512] initial h (null => zeros)
    const float* __restrict__ c0,   // [B][512] initial c (null => zeros)
    float* __restrict__ hs,         // out: (b*96+t)*ostr + j (dir offset pre-added)
    float* __restrict__ cT,         // final c out (stride H2), may be null
    unsigned* __restrict__ flags,   // 64 line-padded flags for this group
    int myblk,
    int ostr, int rev, int j0, float* sm)
{
    float* Hhi = sm;                      // [32][HPAD]
    float* Hlo = sm + 32*HPAD;            // [32][HPAD]
    float* RED = sm + 64*HPAD;            // [8 warps][32*RPAD]
    float* XSM = sm + 64*HPAD + 8*RWARP;  // [4 g][8 u][33 b]
    const int tid  = threadIdx.x;
    const int warp = tid >> 5;

    // ---- stage tf32-rounded U slice into Hhi, preload B fragments ----
    {
        const int r = tid >> 3;                       // gate-row 0..31
        const int gr = (r >> 3) * HH + j0 + (r & 7);  // gate*512 + j0 + unit
        const float* urow = U + (size_t)gr * HH;
#pragma unroll
        for (int q = 0; q < 4; q++) {
            int k = (tid & 7) * 16 + q * 128;
#pragma unroll
            for (int p = 0; p < 4; p++) {
                float4 v = *(const float4*)(urow + k + p * 4);
                float* d = Hhi + r * HPAD + k + p * 4;
                d[0] = wmma::__float_to_tf32(v.x);
                d[1] = wmma::__float_to_tf32(v.y);
                d[2] = wmma::__float_to_tf32(v.z);
                d[3] = wmma::__float_to_tf32(v.w);
            }
        }
    }
    __syncthreads();
    wmma::fragment<wmma::matrix_b, 16, 16, 8, wmma::precision::tf32, wmma::col_major> bfr[8][2];
#pragma unroll
    for (int s = 0; s < 8; s++)
#pragma unroll
        for (int nt = 0; nt < 2; nt++)
            wmma::load_matrix_sync(bfr[s][nt], Hhi + nt * 16 * HPAD + (warp * 8 + s) * 8, HPAD);
    __syncthreads();

    const int pu = tid >> 5;           // unit 0..7
    const int pb = tid & 31;           // batch 0..31
    // xp loader mapping: one float4 per thread, 32B-sector coalesced
    const int xlb = tid >> 3;          // batch 0..31
    const int xr  = tid & 7;
    const int xg  = xr >> 1;           // gate 0..3
    const int xh  = (xr & 1) * 4;      // unit half
    // h stage mapping
    const int sr  = tid >> 3;          // batch row 0..31
    const int sk0 = (tid & 7) * 16;    // k base

    float creg = c0 ? c0[(size_t)pb * HH + j0 + pu] : 0.f;
    const unsigned* myflag = (tid < 64) ? (flags + tid * FSTRIDE) : nullptr;
    unsigned* pubflag = flags + myblk * FSTRIDE;

    for (int t = 0; t < TN; t++) {
        const int tt = rev ? (TN - 1 - t) : t;

        // coalesced xp load (issued before any waiting; consumed at pointwise)
        float4 rx = __ldcg((const float4*)(xp + ((size_t)xlb * TN + tt) * H4
                                              + xg * HH + j0 + xh));

        const float* hb = nullptr;
        size_t hstr = 0;
        if (t == 0) {
            if (h0) { hb = h0; hstr = HH; }
        } else {
            const int tprev = rev ? (tt + 1) : (tt - 1);
            hb = hs + (size_t)tprev * ostr;
            hstr = (size_t)TN * ostr;
        }

        if (hb) {
            if (t > 0) {
                // distributed wait: 64 threads, one line-padded flag each,
                // acquire-load with fast first probe then nanosleep backoff
                if (myflag) {
                    unsigned v = ld_acq(myflag);
                    while (v < (unsigned)t) {
                        __nanosleep(40);
                        v = ld_acq(myflag);
                    }
                }
                __syncthreads();
            }
            // stage h hi/lo: 2 chunks of 8 float4, vectorized stores
            {
                const float* hrow = hb + (size_t)sr * hstr;
#pragma unroll
                for (int ch = 0; ch < 2; ch++) {
                    float4 v[8];
#pragma unroll
                    for (int i = 0; i < 8; i++) {
                        int k = sk0 + (ch * 2 + (i >> 2)) * 128 + (i & 3) * 4;
                        v[i] = __ldcg((const float4*)(hrow + k));
                    }
#pragma unroll
                    for (int i = 0; i < 8; i++) {
                        int k = sk0 + (ch * 2 + (i >> 2)) * 128 + (i & 3) * 4;
                        float4 hi4, lo4;
                        hi4.x = wmma::__float_to_tf32(v[i].x); lo4.x = v[i].x - hi4.x;
                        hi4.y = wmma::__float_to_tf32(v[i].y); lo4.y = v[i].y - hi4.y;
                        hi4.z = wmma::__float_to_tf32(v[i].z); lo4.z = v[i].z - hi4.z;
                        hi4.w = wmma::__float_to_tf32(v[i].w); lo4.w = v[i].w - hi4.w;
                        *(float4*)(Hhi + sr * HPAD + k) = hi4;
                        *(float4*)(Hlo + sr * HPAD + k) = lo4;
                    }
                }
            }
            // stash xp into XSM (consumed after the RED sync)
            XSM[xg * 264 + (xh + 0) * 33 + xlb] = rx.x;
            XSM[xg * 264 + (xh + 1) * 33 + xlb] = rx.y;
            XSM[xg * 264 + (xh + 2) * 33 + xlb] = rx.z;
            XSM[xg * 264 + (xh + 3) * 33 + xlb] = rx.w;
            __syncthreads();

            wmma::fragment<wmma::accumulator, 16, 16, 8, float> acc[2][2];
#pragma unroll
            for (int mt = 0; mt < 2; mt++)
#pragma unroll
                for (int nt = 0; nt < 2; nt++) wmma::fill_fragment(acc[mt][nt], 0.f);

#pragma unroll
            for (int s = 0; s < 8; s++) {
                const int ko = (warp * 8 + s) * 8;
#pragma unroll
                for (int mt = 0; mt < 2; mt++) {
                    wmma::fragment<wmma::matrix_a, 16, 16, 8, wmma::precision::tf32, wmma::row_major> ah, al;
                    wmma::load_matrix_sync(ah, Hhi + mt * 16 * HPAD + ko, HPAD);
                    wmma::load_matrix_sync(al, Hlo + mt * 16 * HPAD + ko, HPAD);
#pragma unroll
                    for (int nt = 0; nt < 2; nt++) {
                        wmma::mma_sync(acc[mt][nt], ah, bfr[s][nt], acc[mt][nt]);
                        wmma::mma_sync(acc[mt][nt], al, bfr[s][nt], acc[mt][nt]);
                    }
                }
            }
#pragma unroll
            for (int mt = 0; mt < 2; mt++)
#pragma unroll
                for (int nt = 0; nt < 2; nt++)
                    wmma::store_matrix_sync(RED + warp * RWARP + (mt * 16) * RPAD + nt * 16,
                                            acc[mt][nt], RPAD, wmma::mem_row_major);
            __syncthreads();
        } else {
            XSM[xg * 264 + (xh + 0) * 33 + xlb] = rx.x;
            XSM[xg * 264 + (xh + 1) * 33 + xlb] = rx.y;
            XSM[xg * 264 + (xh + 2) * 33 + xlb] = rx.z;
            XSM[xg * 264 + (xh + 3) * 33 + xlb] = rx.w;
            __syncthreads();
        }

        float s0 = 0.f, s1 = 0.f, s2 = 0.f, s3 = 0.f;
        if (hb) {
#pragma unroll
            for (int w = 0; w < 8; w++) {
                const float* rp = RED + w * RWARP + pb * RPAD + pu;
                s0 += rp[0]; s1 += rp[8]; s2 += rp[16]; s3 += rp[24];
            }
        }
        {
            float gi = s0 + XSM[pu * 33 + pb];
            float gf = s1 + XSM[264 + pu * 33 + pb];
            float gg = s2 + XSM[528 + pu * 33 + pb];
            float go = s3 + XSM[792 + pu * 33 + pb];
            float si = fast_sigmoid(gi);
            float sf = fast_sigmoid(gf);
            float so = fast_sigmoid(go);
            float tg = fast_tanh(gg);
            creg = sf * creg + si * tg;
            __stcg(hs + ((size_t)pb * TN + tt) * ostr + j0 + pu, so * fast_tanh(creg));
        }
        __syncthreads();
        if (tid == 0) {
            // release-store publish: orders this block's h stores (observed via
            // syncthreads) before the flag update; single writer per flag.
            st_rel(pubflag, (unsigned)(t + 1));
        }
    }

    if (cT) cT[(size_t)pb * H2 + j0 + pu] = creg;
}

__global__ __launch_bounds__(256) void lstm_scan_enc(
    const float* __restrict__ xpf, const float* __restrict__ xpb,
    const float* __restrict__ Uf,  const float* __restrict__ Ub,
    float* __restrict__ hs, float* __restrict__ cT)
{
    extern __shared__ float sm[];
    const int dir = blockIdx.x >> 6;
    const int jb  = blockIdx.x & 63;
    scan_mma(dir ? xpb : xpf, dir ? Ub : Uf, nullptr, nullptr,
             hs + dir * 512, cT + dir * 512,
             d_flag + dir * 64 * FSTRIDE, jb, H2, dir, jb * 8, sm);
}

__global__ __launch_bounds__(256) void lstm_scan_dec(
    const float* __restrict__ xp, const float* __restrict__ U,
    const float* __restrict__ h0, const float* __restrict__ c0,
    float* __restrict__ hs)
{
    extern __shared__ float sm[];
    const int jb = blockIdx.x;
    scan_mma(xp, U, h0, c0, hs, nullptr, d_flag, jb, HH, 0, jb * 8, sm);
}

__global__ void gather_hT(int n) {
    int i = blockIdx.x * blockDim.x + threadIdx.x;
    if (i >= n) return;
    int l = i >> 15;
    int r = i & 32767;
    int b = r >> 10;
    int j = r & 1023;
    const float* src = l ? d_x2 : d_x1;
    int tt = (j < 512) ? (SS - 1) : 0;
    float v = src[((size_t)b * SS + tt) * H2 + j];
    (l ? d_ehT1 : d_ehT0)[b * H2 + j] = v;
}

// ---------------- attention + concat ----------------
__global__ __launch_bounds__(128) void attn_kernel(
    const float* __restrict__ y, const float* __restrict__ enc,
    const int* __restrict__ src_seq, float* __restrict__ comb)
{
    const int bt = blockIdx.x;
    const int b = bt / TN;
    __shared__ float ysm[HH];
    __shared__ float esm[SS];
    __shared__ float red[1];
    const int tid = threadIdx.x;
    const float* yrow = y + (size_t)bt * HH;
#pragma unroll
    for (int i = 0; i < 4; i++) ysm[tid + i * 128] = yrow[tid + i * 128];
    __syncthreads();

    const int lane = tid & 31, w = tid >> 5;
    for (int s = w; s < SS; s += 4) {
        const float* er = enc + ((size_t)b * SS + s) * HH;
        float p = 0.f;
        for (int d = lane; d < HH; d += 32) p += ysm[d] * er[d];
#pragma unroll
        for (int off = 16; off; off >>= 1) p += __shfl_xor_sync(0xffffffffu, p, off);
        if (lane == 0) esm[s] = (src_seq[b * SS + s] != 0) ? p : -1e10f;
    }
    __syncthreads();

    if (w == 0) {
        float m = -1e30f;
        for (int s = lane; s < SS; s += 32) m = fmaxf(m, esm[s]);
#pragma unroll
        for (int off = 16; off; off >>= 1) m = fmaxf(m, __shfl_xor_sync(0xffffffffu, m, off));
        float sum = 0.f;
        for (int s = lane; s < SS; s += 32) { float e = expf(esm[s] - m); esm[s] = e; sum += e; }
#pragma unroll
        for (int off = 16; off; off >>= 1) sum += __shfl_xor_sync(0xffffffffu, sum, off);
        if (lane == 0) red[0] = 1.f / sum;
    }
    __syncthreads();

    const float inv = red[0];
    const int d = tid * 4;
    float4 ctx = make_float4(0.f, 0.f, 0.f, 0.f);
    for (int s = 0; s < SS; s++) {
        float a = esm[s] * inv;
        float4 ev = *(const float4*)(enc + ((size_t)b * SS + s) * HH + d);
        ctx.x += a * ev.x; ctx.y += a * ev.y; ctx.z += a * ev.z; ctx.w += a * ev.w;
    }
    float* crow = comb + (size_t)bt * H2;
#pragma unroll
    for (int i = 0; i < 4; i++) crow[tid + i * 128] = ysm[tid + i * 128];
    *(float4*)(crow + HH + d) = ctx;
}

// ---------------- host launcher ----------------
static float* sym(const void* s) {
    void* p = nullptr;
    cudaGetSymbolAddress(&p, s);
    return (float*)p;
}

#define GEMM_SMEM (4 * 5120 * 4)

extern "C" void kernel_launch(void* const* d_in, const int* in_sizes, int n_in,
                              void* d_out, int out_size) {
    const int*   src_seq = (const int*)d_in[0];
    const int*   trg_seq = (const int*)d_in[1];
    const float* src_emb = (const float*)d_in[2];
    const float* trg_emb = (const float*)d_in[3];
    const float* eW0f = (const float*)d_in[4];
    const float* eU0f = (const float*)d_in[5];
    const float* eb0f = (const float*)d_in[6];
    const float* eW0b = (const float*)d_in[7];
    const float* eU0b = (const float*)d_in[8];
    const float* eb0b = (const float*)d_in[9];
    const float* eW1f = (const float*)d_in[10];
    const float* eU1f = (const float*)d_in[11];
    const float* eb1f = (const float*)d_in[12];
    const float* eW1b = (const float*)d_in[13];
    const float* eU1b = (const float*)d_in[14];
    const float* eb1b = (const float*)d_in[15];
    const float* out_W = (const float*)d_in[16];
    const float* out_b = (const float*)d_in[17];
    const float* hpW  = (const float*)d_in[18];
    const float* hpb  = (const float*)d_in[19];
    const float* cpW  = (const float*)d_in[20];
    const float* cpb  = (const float*)d_in[21];
    const float* dW0  = (const float*)d_in[22];
    const float* dU0  = (const float*)d_in[23];
    const float* db0  = (const float*)d_in[24];
    const float* dW1  = (const float*)d_in[25];
    const float* dU1  = (const float*)d_in[26];
    const float* db1  = (const float*)d_in[27];
    const float* fcW  = (const float*)d_in[28];
    const float* fcb  = (const float*)d_in[29];
    float* out = (float*)d_out;

    float* xsrc = sym(d_xsrc);
    float* ytrg = sym(d_ytrg);
    float* xpf  = sym(d_xpf);
    float* xpb  = sym(d_xpb);
    float* x1   = sym(d_x1);
    float* x2   = sym(d_x2);
    float* enc  = sym(d_enc);
    float* y1   = sym(d_y1);
    float* y2   = sym(d_y2);
    float* comb = sym(d_comb);
    float* ecT0 = sym(d_ecT0);
    float* ecT1 = sym(d_ecT1);
    float* ehT0 = sym(d_ehT0);
    float* ehT1 = sym(d_ehT1);
    float* dh0  = sym(d_dh0);
    float* dh1  = sym(d_dh1);
    float* dc0  = sym(d_dc0);
    float* dc1  = sym(d_dc1);

    static bool attr_done = false;
    if (!attr_done) {
        cudaFuncSetAttribute(gemm_tf32, cudaFuncAttributeMaxDynamicSharedMemorySize, GEMM_SMEM);
        cudaFuncSetAttribute(lstm_scan_enc, cudaFuncAttributeMaxDynamicSharedMemorySize, SCAN_SMEM);
        cudaFuncSetAttribute(lstm_scan_dec, cudaFuncAttributeMaxDynamicSharedMemorySize, SCAN_SMEM);
        attr_done = true;
    }

    embed_kernel<<<(BB*SS*EE + 255)/256, 256>>>(xsrc, src_emb, src_seq, BB*SS*EE);
    embed_kernel<<<(BB*TN*EE + 255)/256, 256>>>(ytrg, trg_emb, trg_seq, BB*TN*EE);

    const dim3 gXP((BB*SS)/128, H4/128);     // (24, 16) M-fast
    const dim3 gENC((BB*SS)/128, HH/128);    // (24, 4)
    const dim3 gP4(HH/128, 1, 4);            // fused 4 projections
    const dim3 gFC((BB*TN)/128, VV/128);     // (24, 250)

    // ===== encoder layer 0 =====
    gemm_tf32<<<gXP, 256, GEMM_SMEM>>>(xsrc, eW0f, eb0f, xpf, BB*SS, H4, EE);
    gemm_tf32<<<gXP, 256, GEMM_SMEM>>>(xsrc, eW0b, eb0b, xpb, BB*SS, H4, EE);
    flag_reset_kernel<<<16, 256>>>();
    lstm_scan_enc<<<128, 256, SCAN_SMEM>>>(xpf, xpb, eU0f, eU0b, x1, ecT0);

    // ===== encoder layer 1 =====
    gemm_tf32<<<gXP, 256, GEMM_SMEM>>>(x1, eW1f, eb1f, xpf, BB*SS, H4, H2);
    gemm_tf32<<<gXP, 256, GEMM_SMEM>>>(x1, eW1b, eb1b, xpb, BB*SS, H4, H2);
    flag_reset_kernel<<<16, 256>>>();
    lstm_scan_enc<<<128, 256, SCAN_SMEM>>>(xpf, xpb, eU1f, eU1b, x2, ecT1);

    gemm_tf32<<<gENC, 256, GEMM_SMEM>>>(x2, out_W, out_b, enc, BB*SS, HH, H2);

    gather_hT<<<(2*BB*H2 + 255)/256, 256>>>(2*BB*H2);
    proj4_kernel<<<gP4, 256>>>(ehT0, ehT1, ecT0, ecT1, hpW, hpb, cpW, cpb,
                               dh0, dh1, dc0, dc1);

    // ===== decoder layer 0 =====
    gemm_tf32<<<gXP, 256, GEMM_SMEM>>>(ytrg, dW0, db0, xpf, BB*TN, H4, EE);
    flag_reset_kernel<<<16, 256>>>();
    lstm_scan_dec<<<64, 256, SCAN_SMEM>>>(xpf, dU0, dh0, dc0, y1);

    // ===== decoder layer 1 =====
    gemm_tf32<<<gXP, 256, GEMM_SMEM>>>(y1, dW1, db1, xpf, BB*TN, H4, HH);
    flag_reset_kernel<<<16, 256>>>();
    lstm_scan_dec<<<64, 256, SCAN_SMEM>>>(xpf, dU1, dh1, dc1, y2);

    // ===== attention + concat =====
    attn_kernel<<<BB*TN, 128>>>(y2, enc, src_seq, comb);

    // ===== final FC on tensor cores (TF32) =====
    gemm_tf32<<<gFC, 256, GEMM_SMEM>>>(comb, fcW, fcb, out, BB*TN, VV, H2);
}

// round 16
// speedup vs baseline: 1.0899x; 1.0899x over previous
#include <cuda_runtime.h>
#include <math.h>
#include <mma.h>
using namespace nvcuda;

#define BB 32
#define SS 96
#define TN 96
#define EE 256
#define HH 512
#define H4 2048
#define H2 1024
#define VV 32000

// ---------------- static scratch (no allocations) ----------------
__device__ float d_xsrc[BB*SS*EE];
__device__ float d_ytrg[BB*TN*EE];
__device__ float d_xpf[BB*SS*H4];
__device__ float d_xpb[BB*SS*H4];
__device__ float d_x1[BB*SS*H2];
__device__ float d_x2[BB*SS*H2];
__device__ float d_enc[BB*SS*HH];
__device__ float d_y1[BB*TN*HH];
__device__ float d_y2[BB*TN*HH];
__device__ float d_comb[BB*TN*H2];
__device__ float d_ecT0[BB*H2];
__device__ float d_ecT1[BB*H2];
__device__ float d_ehT0[BB*H2];
__device__ float d_ehT1[BB*H2];
__device__ float d_dh0[BB*HH];
__device__ float d_dh1[BB*HH];
__device__ float d_dc0[BB*HH];
__device__ float d_dc1[BB*HH];

// per-block step flags; enc: [dir*64+jblk]; fused dec: dec0=0..63, dec1=64..127
__device__ unsigned d_flag[128];

__global__ void flag_reset_kernel() {
    if (threadIdx.x < 128) d_flag[threadIdx.x] = 0u;
}

// ---------------- helpers ----------------
__global__ void embed_kernel(float* __restrict__ out, const float* __restrict__ emb,
                             const int* __restrict__ seq, int n) {
    int i = blockIdx.x * blockDim.x + threadIdx.x;
    if (i < n) {
        int tok = seq[i >> 8];
        out[i] = emb[(size_t)tok * EE + (i & 255)];
    }
}

// ---------------- fused 4x small projection (M=32, N=512, K=1024) ----------------
__global__ __launch_bounds__(256) void proj4_kernel(
    const float* __restrict__ A0, const float* __restrict__ A1,
    const float* __restrict__ A2, const float* __restrict__ A3,
    const float* __restrict__ hpW, const float* __restrict__ hpb,
    const float* __restrict__ cpW, const float* __restrict__ cpb,
    float* __restrict__ C0, float* __restrict__ C1,
    float* __restrict__ C2, float* __restrict__ C3)
{
    const float* A; const float* W; const float* bias; float* C;
    switch (blockIdx.z) {
        case 0: A = A0; W = hpW;            bias = hpb;      C = C0; break;
        case 1: A = A1; W = hpW + HH*H2;    bias = hpb + HH; C = C1; break;
        case 2: A = A2; W = cpW;            bias = cpb;      C = C2; break;
        default:A = A3; W = cpW + HH*H2;    bias = cpb + HH; C = C3; break;
    }
    const int M = BB, N = HH, K = H2;

    __shared__ float As[16][132];
    __shared__ float Ws[16][132];
    const int bn = blockIdx.x * 128;
    const int tid = threadIdx.x;
    const int trow = (tid >> 4) * 8;
    const int tcol = (tid & 15) * 8;

    float acc[8][8];
#pragma unroll
    for (int i = 0; i < 8; i++)
#pragma unroll
        for (int j = 0; j < 8; j++) acc[i][j] = 0.f;

    for (int k0 = 0; k0 < K; k0 += 16) {
#pragma unroll
        for (int i = 0; i < 2; i++) {
            int q = tid + i * 256;
            int r = q >> 2;
            int c = (q & 3) * 4;
            float4 v = make_float4(0.f, 0.f, 0.f, 0.f);
            if (r < M) v = *(const float4*)(A + (size_t)r * K + k0 + c);
            As[c + 0][r] = v.x; As[c + 1][r] = v.y; As[c + 2][r] = v.z; As[c + 3][r] = v.w;
            float4 u = *(const float4*)(W + (size_t)(bn + r) * K + k0 + c);
            Ws[c + 0][r] = u.x; Ws[c + 1][r] = u.y; Ws[c + 2][r] = u.z; Ws[c + 3][r] = u.w;
        }
        __syncthreads();
#pragma unroll
        for (int kk = 0; kk < 16; kk++) {
            float4 a0 = *(const float4*)&As[kk][trow];
            float4 a1 = *(const float4*)&As[kk][trow + 4];
            float4 b0 = *(const float4*)&Ws[kk][tcol];
            float4 b1 = *(const float4*)&Ws[kk][tcol + 4];
            float av[8] = {a0.x, a0.y, a0.z, a0.w, a1.x, a1.y, a1.z, a1.w};
            float bv[8] = {b0.x, b0.y, b0.z, b0.w, b1.x, b1.y, b1.z, b1.w};
#pragma unroll
            for (int i = 0; i < 8; i++)
#pragma unroll
                for (int j = 0; j < 8; j++) acc[i][j] += av[i] * bv[j];
        }
        __syncthreads();
    }

    float bb[8];
#pragma unroll
    for (int j = 0; j < 8; j++) bb[j] = bias[bn + tcol + j];
#pragma unroll
    for (int i = 0; i < 8; i++) {
        int r = trow + i;
        if (r < M) {
            float* cp = C + (size_t)r * N + bn + tcol;
#pragma unroll
            for (int j = 0; j < 8; j += 4) {
                float4 v;
                v.x = acc[i][j + 0] + bb[j + 0];
                v.y = acc[i][j + 1] + bb[j + 1];
                v.z = acc[i][j + 2] + bb[j + 2];
                v.w = acc[i][j + 3] + bb[j + 3];
                *(float4*)(cp + j) = v;
            }
        }
    }
}

// ---------------- TF32 tensor-core GEMM (FC + big projections) ----------------
__global__ __launch_bounds__(256) void gemm_tf32(
    const float* __restrict__ A, const float* __restrict__ W,
    const float* __restrict__ bias, float* __restrict__ C,
    int M, int N, int K)
{
    extern __shared__ float sm[];
    float* Ab[2] = { sm,          sm + 5120 };
    float* Bb[2] = { sm + 10240,  sm + 15360 };

    const int bm = blockIdx.x * 128;
    const int bn = blockIdx.y * 128;
    const int tid  = threadIdx.x;
    const int warp = tid >> 5;
    const int lane = tid & 31;
    const int wm = warp & 3;
    const int wn = warp >> 2;

    wmma::fragment<wmma::accumulator, 16, 16, 8, float> c[2][4];
#pragma unroll
    for (int i = 0; i < 2; i++)
#pragma unroll
        for (int j = 0; j < 4; j++) wmma::fill_fragment(c[i][j], 0.f);

    const int lr = tid >> 1;
    const int lc = (tid & 1) * 16;
    const float* ap = A + (size_t)(bm + lr) * K + lc;
    const float* wp = W + (size_t)(bn + lr) * K + lc;

    float4 ra[4], rw[4];
#pragma unroll
    for (int q = 0; q < 4; q++) {
        ra[q] = *(const float4*)(ap + q * 4);
        rw[q] = *(const float4*)(wp + q * 4);
    }
    {
        float* ad = Ab[0] + lr * 40 + lc;
        float* bd = Bb[0] + lr * 40 + lc;
#pragma unroll
        for (int q = 0; q < 4; q++) {
            ad[q*4+0] = wmma::__float_to_tf32(ra[q].x);
            ad[q*4+1] = wmma::__float_to_tf32(ra[q].y);
            ad[q*4+2] = wmma::__float_to_tf32(ra[q].z);
            ad[q*4+3] = wmma::__float_to_tf32(ra[q].w);
            bd[q*4+0] = wmma::__float_to_tf32(rw[q].x);
            bd[q*4+1] = wmma::__float_to_tf32(rw[q].y);
            bd[q*4+2] = wmma::__float_to_tf32(rw[q].z);
            bd[q*4+3] = wmma::__float_to_tf32(rw[q].w);
        }
    }
    __syncthreads();

    const int ksteps = K >> 5;
    int cur = 0;
    for (int ks = 0; ks < ksteps; ks++) {
        const bool more = (ks + 1 < ksteps);
        if (more) {
            const float* a2 = ap + (ks + 1) * 32;
            const float* w2 = wp + (ks + 1) * 32;
#pragma unroll
            for (int q = 0; q < 4; q++) {
                ra[q] = *(const float4*)(a2 + q * 4);
                rw[q] = *(const float4*)(w2 + q * 4);
            }
        }
        const float* As = Ab[cur];
        const float* Bs = Bb[cur];
#pragma unroll
        for (int kk = 0; kk < 4; kk++) {
            wmma::fragment<wmma::matrix_a, 16, 16, 8, wmma::precision::tf32, wmma::row_major> a[2];
            wmma::fragment<wmma::matrix_b, 16, 16, 8, wmma::precision::tf32, wmma::col_major> b[4];
#pragma unroll
            for (int i = 0; i < 2; i++)
                wmma::load_matrix_sync(a[i], As + (wm * 32 + i * 16) * 40 + kk * 8, 40);
#pragma unroll
            for (int j = 0; j < 4; j++)
                wmma::load_matrix_sync(b[j], Bs + (wn * 64 + j * 16) * 40 + kk * 8, 40);
#pragma unroll
            for (int i = 0; i < 2; i++)
#pragma unroll
                for (int j = 0; j < 4; j++)
                    wmma::mma_sync(c[i][j], a[i], b[j], c[i][j]);
        }
        if (more) {
            float* ad = Ab[cur ^ 1] + lr * 40 + lc;
            float* bd = Bb[cur ^ 1] + lr * 40 + lc;
#pragma unroll
            for (int q = 0; q < 4; q++) {
                ad[q*4+0] = wmma::__float_to_tf32(ra[q].x);
                ad[q*4+1] = wmma::__float_to_tf32(ra[q].y);
                ad[q*4+2] = wmma::__float_to_tf32(ra[q].z);
                ad[q*4+3] = wmma::__float_to_tf32(ra[q].w);
                bd[q*4+0] = wmma::__float_to_tf32(rw[q].x);
                bd[q*4+1] = wmma::__float_to_tf32(rw[q].y);
                bd[q*4+2] = wmma::__float_to_tf32(rw[q].z);
                bd[q*4+3] = wmma::__float_to_tf32(rw[q].w);
            }
            __syncthreads();
            cur ^= 1;
        }
    }
    __syncthreads();

    float* wbuf = sm + warp * 320;
    const int er = lane >> 1;
    const int ec = (lane & 1) * 8;
#pragma unroll
    for (int i = 0; i < 2; i++) {
#pragma unroll
        for (int j = 0; j < 4; j++) {
            wmma::store_matrix_sync(wbuf, c[i][j], 20, wmma::mem_row_major);
            __syncwarp();
            const int gr = bm + wm * 32 + i * 16 + er;
            const int gc = bn + wn * 64 + j * 16 + ec;
            const float* bp = bias + gc;
            float* dst = C + (size_t)gr * N + gc;
            float4 v0, v1;
            v0.x = wbuf[er * 20 + ec + 0] + bp[0];
            v0.y = wbuf[er * 20 + ec + 1] + bp[1];
            v0.z = wbuf[er * 20 + ec + 2] + bp[2];
            v0.w = wbuf[er * 20 + ec + 3] + bp[3];
            v1.x = wbuf[er * 20 + ec + 4] + bp[4];
            v1.y = wbuf[er * 20 + ec + 5] + bp[5];
            v1.z = wbuf[er * 20 + ec + 6] + bp[6];
            v1.w = wbuf[er * 20 + ec + 7] + bp[7];
            *(float4*)(dst)     = v0;
            *(float4*)(dst + 4) = v1;
            __syncwarp();
        }
    }
}

// ---------------- persistent LSTM scan: tensor-core gemv (R10-proven body) ----------------
#define HPAD 520
#define RPAD 36
#define RWARP (32*RPAD)
#define SCAN_SMEM ((2*32*HPAD + 8*RWARP) * 4)

// stage tf32-rounded 32x512 weight slice (rows = gate*512+j0+unit) into Hhi
__device__ __forceinline__ void stage_w_tf32(const float* __restrict__ U, int j0,
                                             float* __restrict__ Hhi, int tid)
{
    const int r = tid >> 3;
    const int gr = (r >> 3) * HH + j0 + (r & 7);
    const float* urow = U + (size_t)gr * HH;
#pragma unroll
    for (int q = 0; q < 4; q++) {
        int k = (tid & 7) * 16 + q * 128;
#pragma unroll
        for (int p = 0; p < 4; p++) {
            float4 v = *(const float4*)(urow + k + p * 4);
            float* d = Hhi + r * HPAD + k + p * 4;
            d[0] = wmma::__float_to_tf32(v.x);
            d[1] = wmma::__float_to_tf32(v.y);
            d[2] = wmma::__float_to_tf32(v.z);
            d[3] = wmma::__float_to_tf32(v.w);
        }
    }
}

__device__ __forceinline__ void scan_mma(
    const float* __restrict__ xp,   // [B][96][2048] for this dir
    const float* __restrict__ U,    // [2048][512]
    const float* __restrict__ h0,   // [B][512] initial h (null => zeros)
    const float* __restrict__ c0,   // [B][512] initial c (null => zeros)
    float* __restrict__ hs,         // out: (b*96+t)*ostr + j (dir offset pre-added)
    float* __restrict__ cT,         // final c out (stride H2), may be null
    unsigned* __restrict__ flags,   // 64 flags for this group
    int myblk,
    int ostr, int rev, int j0, float* sm)
{
    float* Hhi = sm;                 // [32][HPAD]
    float* Hlo = sm + 32*HPAD;       // [32][HPAD]
    float* RED = sm + 64*HPAD;       // [8 warps][32*RPAD]
    const int tid  = threadIdx.x;
    const int warp = tid >> 5;

    stage_w_tf32(U, j0, Hhi, tid);
    __syncthreads();
    wmma::fragment<wmma::matrix_b, 16, 16, 8, wmma::precision::tf32, wmma::col_major> bfr[8][2];
#pragma unroll
    for (int s = 0; s < 8; s++)
#pragma unroll
        for (int nt = 0; nt < 2; nt++)
            wmma::load_matrix_sync(bfr[s][nt], Hhi + nt * 16 * HPAD + (warp * 8 + s) * 8, HPAD);
    __syncthreads();

    const int pu = tid >> 5;           // unit 0..7
    const int pb = tid & 31;           // batch 0..31
    float creg = c0 ? c0[(size_t)pb * HH + j0 + pu] : 0.f;
    volatile unsigned* myflag = (tid < 64) ? (flags + tid) : nullptr;

    for (int t = 0; t < TN; t++) {
        const int tt = rev ? (TN - 1 - t) : t;
        const size_t xb = ((size_t)pb * TN + tt) * H4 + j0 + pu;
        const float xgi = xp[xb];
        const float xgf = xp[xb + 512];
        const float xgg = xp[xb + 1024];
        const float xgo = xp[xb + 1536];

        const float* hb = nullptr;
        size_t hstr = 0;
        if (t == 0) {
            if (h0) { hb = h0; hstr = HH; }
        } else {
            const int tprev = rev ? (tt + 1) : (tt - 1);
            hb = hs + (size_t)tprev * ostr;
            hstr = (size_t)TN * ostr;
        }

        if (hb) {
            if (t > 0) {
                if (myflag) { while (*myflag < (unsigned)t) { } }
                __syncthreads();
            }
            // stage h hi/lo
            {
                const int r = tid >> 3;                   // batch row
                const float* hrow = hb + (size_t)r * hstr;
#pragma unroll
                for (int q = 0; q < 4; q++) {
                    int k = (tid & 7) * 16 + q * 128;
#pragma unroll
                    for (int p = 0; p < 4; p++) {
                        float4 v = __ldcg((const float4*)(hrow + k + p * 4));
                        float* dh = Hhi + r * HPAD + k + p * 4;
                        float* dl = Hlo + r * HPAD + k + p * 4;
                        float hx = wmma::__float_to_tf32(v.x);
                        float hy = wmma::__float_to_tf32(v.y);
                        float hz = wmma::__float_to_tf32(v.z);
                        float hw = wmma::__float_to_tf32(v.w);
                        dh[0] = hx; dl[0] = v.x - hx;
                        dh[1] = hy; dl[1] = v.y - hy;
                        dh[2] = hz; dl[2] = v.z - hz;
                        dh[3] = hw; dl[3] = v.w - hw;
                    }
                }
            }
            __syncthreads();

            wmma::fragment<wmma::accumulator, 16, 16, 8, float> acc[2][2];
#pragma unroll
            for (int mt = 0; mt < 2; mt++)
#pragma unroll
                for (int nt = 0; nt < 2; nt++) wmma::fill_fragment(acc[mt][nt], 0.f);

#pragma unroll
            for (int s = 0; s < 8; s++) {
                const int ko = (warp * 8 + s) * 8;
#pragma unroll
                for (int mt = 0; mt < 2; mt++) {
                    wmma::fragment<wmma::matrix_a, 16, 16, 8, wmma::precision::tf32, wmma::row_major> ah, al;
                    wmma::load_matrix_sync(ah, Hhi + mt * 16 * HPAD + ko, HPAD);
                    wmma::load_matrix_sync(al, Hlo + mt * 16 * HPAD + ko, HPAD);
#pragma unroll
                    for (int nt = 0; nt < 2; nt++) {
                        wmma::mma_sync(acc[mt][nt], ah, bfr[s][nt], acc[mt][nt]);
                        wmma::mma_sync(acc[mt][nt], al, bfr[s][nt], acc[mt][nt]);
                    }
                }
            }
#pragma unroll
            for (int mt = 0; mt < 2; mt++)
#pragma unroll
                for (int nt = 0; nt < 2; nt++)
                    wmma::store_matrix_sync(RED + warp * RWARP + (mt * 16) * RPAD + nt * 16,
                                            acc[mt][nt], RPAD, wmma::mem_row_major);
            __syncthreads();
        }

        float s0 = 0.f, s1 = 0.f, s2 = 0.f, s3 = 0.f;
        if (hb) {
#pragma unroll
            for (int w = 0; w < 8; w++) {
                const float* rp = RED + w * RWARP + pb * RPAD + pu;
                s0 += rp[0]; s1 += rp[8]; s2 += rp[16]; s3 += rp[24];
            }
        }
        {
            float gi = s0 + xgi;
            float gf = s1 + xgf;
            float gg = s2 + xgg;
            float go = s3 + xgo;
            float si = 1.f / (1.f + expf(-gi));
            float sf = 1.f / (1.f + expf(-gf));
            float so = 1.f / (1.f + expf(-go));
            float tg = tanhf(gg);
            creg = sf * creg + si * tg;
            __stcg(hs + ((size_t)pb * TN + tt) * ostr + j0 + pu, so * tanhf(creg));
        }
        __syncthreads();
        if (tid == 0) {
            __threadfence();
            atomicExch(&flags[myblk], (unsigned)(t + 1));
        }
    }

    if (cT) cT[(size_t)pb * H2 + j0 + pu] = creg;
}

// ---------------- decoder layer-1 scan: dual-gemv (y-projection + recurrence) ----------------
// Runs 1 step behind layer 0. gates = y1[t]@Wy^T + h[t-1]@Uh^T + bias.
__device__ __forceinline__ void scan_mma_l1(
    const float* __restrict__ ysrc,  // [B][96][512] layer-0 output
    const float* __restrict__ Wy,    // dW1 [2048][512]
    const float* __restrict__ Uh,    // dU1 [2048][512]
    const float* __restrict__ bias,  // db1 [2048]
    const float* __restrict__ h0,    // [B][512]
    const float* __restrict__ c0,    // [B][512]
    float* __restrict__ hs,          // y2 out [B][96][512]
    unsigned* __restrict__ flagsA,   // dec0 flags (64)
    unsigned* __restrict__ flagsB,   // dec1 flags (64)
    int myblk, int j0, float* sm)
{
    float* Hhi = sm;
    float* Hlo = sm + 32*HPAD;
    float* RED = sm + 64*HPAD;
    const int tid  = threadIdx.x;
    const int warp = tid >> 5;

    // preload both weight sets' B fragments (Uh -> bU, Wy -> bW) via Hhi staging
    wmma::fragment<wmma::matrix_b, 16, 16, 8, wmma::precision::tf32, wmma::col_major> bU[8][2], bW[8][2];
    stage_w_tf32(Uh, j0, Hhi, tid);
    __syncthreads();
#pragma unroll
    for (int s = 0; s < 8; s++)
#pragma unroll
        for (int nt = 0; nt < 2; nt++)
            wmma::load_matrix_sync(bU[s][nt], Hhi + nt * 16 * HPAD + (warp * 8 + s) * 8, HPAD);
    __syncthreads();
    stage_w_tf32(Wy, j0, Hhi, tid);
    __syncthreads();
#pragma unroll
    for (int s = 0; s < 8; s++)
#pragma unroll
        for (int nt = 0; nt < 2; nt++)
            wmma::load_matrix_sync(bW[s][nt], Hhi + nt * 16 * HPAD + (warp * 8 + s) * 8, HPAD);
    __syncthreads();

    const int pu = tid >> 5;
    const int pb = tid & 31;
    const float bi = bias[j0 + pu];
    const float bf = bias[512 + j0 + pu];
    const float bg = bias[1024 + j0 + pu];
    const float bo = bias[1536 + j0 + pu];
    float creg = c0[(size_t)pb * HH + j0 + pu];
    volatile unsigned* pollA = (tid < 64) ? (flagsA + tid) : nullptr;
    volatile unsigned* pollB = (tid >= 64 && tid < 128) ? (flagsB + (tid - 64)) : nullptr;

    const int sr  = tid >> 3;          // staging batch row
    const int sk0 = (tid & 7) * 16;    // staging k base

    for (int t = 0; t < TN; t++) {
        // wait: y1[t] ready (dec0 >= t+1) and h[t-1] ready (dec1 peers >= t)
        if (pollA) { while (*pollA < (unsigned)(t + 1)) { } }
        if (pollB && t > 0) { while (*pollB < (unsigned)t) { } }
        __syncthreads();

        wmma::fragment<wmma::accumulator, 16, 16, 8, float> acc[2][2];
#pragma unroll
        for (int mt = 0; mt < 2; mt++)
#pragma unroll
            for (int nt = 0; nt < 2; nt++) wmma::fill_fragment(acc[mt][nt], 0.f);

        // ---- pass Y: stage tf32(y1[t]) into Hhi, mma with bW ----
        {
            const float* yrow = ysrc + ((size_t)sr * TN + t) * HH;
#pragma unroll
            for (int q = 0; q < 4; q++) {
                int k = sk0 + q * 128;
#pragma unroll
                for (int p = 0; p < 4; p++) {
                    float4 v = __ldcg((const float4*)(yrow + k + p * 4));
                    float* d = Hhi + sr * HPAD + k + p * 4;
                    d[0] = wmma::__float_to_tf32(v.x);
                    d[1] = wmma::__float_to_tf32(v.y);
                    d[2] = wmma::__float_to_tf32(v.z);
                    d[3] = wmma::__float_to_tf32(v.w);
                }
            }
        }
        __syncthreads();
#pragma unroll
        for (int s = 0; s < 8; s++) {
            const int ko = (warp * 8 + s) * 8;
#pragma unroll
            for (int mt = 0; mt < 2; mt++) {
                wmma::fragment<wmma::matrix_a, 16, 16, 8, wmma::precision::tf32, wmma::row_major> ay;
                wmma::load_matrix_sync(ay, Hhi + mt * 16 * HPAD + ko, HPAD);
#pragma unroll
                for (int nt = 0; nt < 2; nt++)
                    wmma::mma_sync(acc[mt][nt], ay, bW[s][nt], acc[mt][nt]);
            }
        }
        __syncthreads();   // all fragment loads done; Hhi free for reuse

        // ---- pass H: stage h[t-1] hi/lo, mma with bU (accumulate) ----
        {
            const float* hb = (t == 0) ? h0 : (hs + (size_t)(t - 1) * HH);
            const size_t hstr = (t == 0) ? (size_t)HH : (size_t)TN * HH;
            const float* hrow = hb + (size_t)sr * hstr;
#pragma unroll
            for (int q = 0; q < 4; q++) {
                int k = sk0 + q * 128;
#pragma unroll
                for (int p = 0; p < 4; p++) {
                    float4 v = __ldcg((const float4*)(hrow + k + p * 4));
                    float* dh = Hhi + sr * HPAD + k + p * 4;
                    float* dl = Hlo + sr * HPAD + k + p * 4;
                    float hx = wmma::__float_to_tf32(v.x);
                    float hy = wmma::__float_to_tf32(v.y);
                    float hz = wmma::__float_to_tf32(v.z);
                    float hw = wmma::__float_to_tf32(v.w);
                    dh[0] = hx; dl[0] = v.x - hx;
                    dh[1] = hy; dl[1] = v.y - hy;
                    dh[2] = hz; dl[2] = v.z - hz;
                    dh[3] = hw; dl[3] = v.w - hw;
                }
            }
        }
        __syncthreads();
#pragma unroll
        for (int s = 0; s < 8; s++) {
            const int ko = (warp * 8 + s) * 8;
#pragma unroll
            for (int mt = 0; mt < 2; mt++) {
                wmma::fragment<wmma::matrix_a, 16, 16, 8, wmma::precision::tf32, wmma::row_major> ah, al;
                wmma::load_matrix_sync(ah, Hhi + mt * 16 * HPAD + ko, HPAD);
                wmma::load_matrix_sync(al, Hlo + mt * 16 * HPAD + ko, HPAD);
#pragma unroll
                for (int nt = 0; nt < 2; nt++) {
                    wmma::mma_sync(acc[mt][nt], ah, bU[s][nt], acc[mt][nt]);
                    wmma::mma_sync(acc[mt][nt], al, bU[s][nt], acc[mt][nt]);
                }
            }
        }
#pragma unroll
        for (int mt = 0; mt < 2; mt++)
#pragma unroll
            for (int nt = 0; nt < 2; nt++)
                wmma::store_matrix_sync(RED + warp * RWARP + (mt * 16) * RPAD + nt * 16,
                                        acc[mt][nt], RPAD, wmma::mem_row_major);
        __syncthreads();

        float s0 = 0.f, s1 = 0.f, s2 = 0.f, s3 = 0.f;
#pragma unroll
        for (int w = 0; w < 8; w++) {
            const float* rp = RED + w * RWARP + pb * RPAD + pu;
            s0 += rp[0]; s1 += rp[8]; s2 += rp[16]; s3 += rp[24];
        }
        {
            float gi = s0 + bi;
            float gf = s1 + bf;
            float gg = s2 + bg;
            float go = s3 + bo;
            float si = 1.f / (1.f + expf(-gi));
            float sf = 1.f / (1.f + expf(-gf));
            float so = 1.f / (1.f + expf(-go));
            float tg = tanhf(gg);
            creg = sf * creg + si * tg;
            __stcg(hs + ((size_t)pb * TN + t) * HH + j0 + pu, so * tanhf(creg));
        }
        __syncthreads();
        if (tid == 0) {
            __threadfence();
            atomicExch(&flagsB[myblk], (unsigned)(t + 1));
        }
    }
}

__global__ __launch_bounds__(256) void lstm_scan_enc(
    const float* __restrict__ xpf, const float* __restrict__ xpb,
    const float* __restrict__ Uf,  const float* __restrict__ Ub,
    float* __restrict__ hs, float* __restrict__ cT)
{
    extern __shared__ float sm[];
    const int dir = blockIdx.x >> 6;
    const int jb  = blockIdx.x & 63;
    scan_mma(dir ? xpb : xpf, dir ? Ub : Uf, nullptr, nullptr,
             hs + dir * 512, cT + dir * 512,
             d_flag + dir * 64, jb, H2, dir, jb * 8, sm);
}

// fused decoder: blocks 0-63 layer0 (xp precomputed), 64-127 layer1 (skewed)
__global__ __launch_bounds__(256) void lstm_scan_dec_fused(
    const float* __restrict__ xp0,
    const float* __restrict__ dU0,
    const float* __restrict__ dW1, const float* __restrict__ dU1,
    const float* __restrict__ db1,
    const float* __restrict__ dh0, const float* __restrict__ dh1,
    const float* __restrict__ dc0, const float* __restrict__ dc1,
    float* __restrict__ y1, float* __restrict__ y2)
{
    extern __shared__ float sm[];
    const int layer = blockIdx.x >> 6;
    const int jb = blockIdx.x & 63;
    if (layer == 0)
        scan_mma(xp0, dU0, dh0, dc0, y1, nullptr, d_flag, jb, HH, 0, jb * 8, sm);
    else
        scan_mma_l1(y1, dW1, dU1, db1, dh1, dc1, y2,
                    d_flag, d_flag + 64, jb, jb * 8, sm);
}

__global__ void gather_hT(int n) {
    int i = blockIdx.x * blockDim.x + threadIdx.x;
    if (i >= n) return;
    int l = i >> 15;
    int r = i & 32767;
    int b = r >> 10;
    int j = r & 1023;
    const float* src = l ? d_x2 : d_x1;
    int tt = (j < 512) ? (SS - 1) : 0;
    float v = src[((size_t)b * SS + tt) * H2 + j];
    (l ? d_ehT1 : d_ehT0)[b * H2 + j] = v;
}

// ---------------- attention + concat ----------------
__global__ __launch_bounds__(128) void attn_kernel(
    const float* __restrict__ y, const float* __restrict__ enc,
    const int* __restrict__ src_seq, float* __restrict__ comb)
{
    const int bt = blockIdx.x;
    const int b = bt / TN;
    __shared__ float ysm[HH];
    __shared__ float esm[SS];
    __shared__ float red[1];
    const int tid = threadIdx.x;
    const float* yrow = y + (size_t)bt * HH;
#pragma unroll
    for (int i = 0; i < 4; i++) ysm[tid + i * 128] = yrow[tid + i * 128];
    __syncthreads();

    const int lane = tid & 31, w = tid >> 5;
    for (int s = w; s < SS; s += 4) {
        const float* er = enc + ((size_t)b * SS + s) * HH;
        float p = 0.f;
        for (int d = lane; d < HH; d += 32) p += ysm[d] * er[d];
#pragma unroll
        for (int off = 16; off; off >>= 1) p += __shfl_xor_sync(0xffffffffu, p, off);
        if (lane == 0) esm[s] = (src_seq[b * SS + s] != 0) ? p : -1e10f;
    }
    __syncthreads();

    if (w == 0) {
        float m = -1e30f;
        for (int s = lane; s < SS; s += 32) m = fmaxf(m, esm[s]);
#pragma unroll
        for (int off = 16; off; off >>= 1) m = fmaxf(m, __shfl_xor_sync(0xffffffffu, m, off));
        float sum = 0.f;
        for (int s = lane; s < SS; s += 32) { float e = expf(esm[s] - m); esm[s] = e; sum += e; }
#pragma unroll
        for (int off = 16; off; off >>= 1) sum += __shfl_xor_sync(0xffffffffu, sum, off);
        if (lane == 0) red[0] = 1.f / sum;
    }
    __syncthreads();

    const float inv = red[0];
    const int d = tid * 4;
    float4 ctx = make_float4(0.f, 0.f, 0.f, 0.f);
    for (int s = 0; s < SS; s++) {
        float a = esm[s] * inv;
        float4 ev = *(const float4*)(enc + ((size_t)b * SS + s) * HH + d);
        ctx.x += a * ev.x; ctx.y += a * ev.y; ctx.z += a * ev.z; ctx.w += a * ev.w;
    }
    float* crow = comb + (size_t)bt * H2;
#pragma unroll
    for (int i = 0; i < 4; i++) crow[tid + i * 128] = ysm[tid + i * 128];
    *(float4*)(crow + HH + d) = ctx;
}

// ---------------- host launcher ----------------
static float* sym(const void* s) {
    void* p = nullptr;
    cudaGetSymbolAddress(&p, s);
    return (float*)p;
}

#define GEMM_SMEM (4 * 5120 * 4)

extern "C" void kernel_launch(void* const* d_in, const int* in_sizes, int n_in,
                              void* d_out, int out_size) {
    const int*   src_seq = (const int*)d_in[0];
    const int*   trg_seq = (const int*)d_in[1];
    const float* src_emb = (const float*)d_in[2];
    const float* trg_emb = (const float*)d_in[3];
    const float* eW0f = (const float*)d_in[4];
    const float* eU0f = (const float*)d_in[5];
    const float* eb0f = (const float*)d_in[6];
    const float* eW0b = (const float*)d_in[7];
    const float* eU0b = (const float*)d_in[8];
    const float* eb0b = (const float*)d_in[9];
    const float* eW1f = (const float*)d_in[10];
    const float* eU1f = (const float*)d_in[11];
    const float* eb1f = (const float*)d_in[12];
    const float* eW1b = (const float*)d_in[13];
    const float* eU1b = (const float*)d_in[14];
    const float* eb1b = (const float*)d_in[15];
    const float* out_W = (const float*)d_in[16];
    const float* out_b = (const float*)d_in[17];
    const float* hpW  = (const float*)d_in[18];
    const float* hpb  = (const float*)d_in[19];
    const float* cpW  = (const float*)d_in[20];
    const float* cpb  = (const float*)d_in[21];
    const float* dW0  = (const float*)d_in[22];
    const float* dU0  = (const float*)d_in[23];
    const float* db0  = (const float*)d_in[24];
    const float* dW1  = (const float*)d_in[25];
    const float* dU1  = (const float*)d_in[26];
    const float* db1  = (const float*)d_in[27];
    const float* fcW  = (const float*)d_in[28];
    const float* fcb  = (const float*)d_in[29];
    float* out = (float*)d_out;

    float* xsrc = sym(d_xsrc);
    float* ytrg = sym(d_ytrg);
    float* xpf  = sym(d_xpf);
    float* xpb  = sym(d_xpb);
    float* x1   = sym(d_x1);
    float* x2   = sym(d_x2);
    float* enc  = sym(d_enc);
    float* y1   = sym(d_y1);
    float* y2   = sym(d_y2);
    float* comb = sym(d_comb);
    float* ecT0 = sym(d_ecT0);
    float* ecT1 = sym(d_ecT1);
    float* ehT0 = sym(d_ehT0);
    float* ehT1 = sym(d_ehT1);
    float* dh0  = sym(d_dh0);
    float* dh1  = sym(d_dh1);
    float* dc0  = sym(d_dc0);
    float* dc1  = sym(d_dc1);

    static bool attr_done = false;
    if (!attr_done) {
        cudaFuncSetAttribute(gemm_tf32, cudaFuncAttributeMaxDynamicSharedMemorySize, GEMM_SMEM);
        cudaFuncSetAttribute(lstm_scan_enc, cudaFuncAttributeMaxDynamicSharedMemorySize, SCAN_SMEM);
        cudaFuncSetAttribute(lstm_scan_dec_fused, cudaFuncAttributeMaxDynamicSharedMemorySize, SCAN_SMEM);
        attr_done = true;
    }

    embed_kernel<<<(BB*SS*EE + 255)/256, 256>>>(xsrc, src_emb, src_seq, BB*SS*EE);
    embed_kernel<<<(BB*TN*EE + 255)/256, 256>>>(ytrg, trg_emb, trg_seq, BB*TN*EE);

    const dim3 gXP((BB*SS)/128, H4/128);     // (24, 16) M-fast
    const dim3 gENC((BB*SS)/128, HH/128);    // (24, 4)
    const dim3 gP4(HH/128, 1, 4);            // fused 4 projections
    const dim3 gFC((BB*TN)/128, VV/128);     // (24, 250)

    // ===== encoder layer 0 =====
    gemm_tf32<<<gXP, 256, GEMM_SMEM>>>(xsrc, eW0f, eb0f, xpf, BB*SS, H4, EE);
    gemm_tf32<<<gXP, 256, GEMM_SMEM>>>(xsrc, eW0b, eb0b, xpb, BB*SS, H4, EE);
    flag_reset_kernel<<<1, 128>>>();
    lstm_scan_enc<<<128, 256, SCAN_SMEM>>>(xpf, xpb, eU0f, eU0b, x1, ecT0);

    // ===== encoder layer 1 =====
    gemm_tf32<<<gXP, 256, GEMM_SMEM>>>(x1, eW1f, eb1f, xpf, BB*SS, H4, H2);
    gemm_tf32<<<gXP, 256, GEMM_SMEM>>>(x1, eW1b, eb1b, xpb, BB*SS, H4, H2);
    flag_reset_kernel<<<1, 128>>>();
    lstm_scan_enc<<<128, 256, SCAN_SMEM>>>(xpf, xpb, eU1f, eU1b, x2, ecT1);

    gemm_tf32<<<gENC, 256, GEMM_SMEM>>>(x2, out_W, out_b, enc, BB*SS, HH, H2);

    gather_hT<<<(2*BB*H2 + 255)/256, 256>>>(2*BB*H2);
    proj4_kernel<<<gP4, 256>>>(ehT0, ehT1, ecT0, ecT1, hpW, hpb, cpW, cpb,
                               dh0, dh1, dc0, dc1);

    // ===== fused decoder (both layers, 1-step skew pipeline) =====
    gemm_tf32<<<gXP, 256, GEMM_SMEM>>>(ytrg, dW0, db0, xpf, BB*TN, H4, EE);
    flag_reset_kernel<<<1, 128>>>();
    lstm_scan_dec_fused<<<128, 256, SCAN_SMEM>>>(xpf, dU0, dW1, dU1, db1,
                                                 dh0, dh1, dc0, dc1, y1, y2);

    // ===== attention + concat =====
    attn_kernel<<<BB*TN, 128>>>(y2, enc, src_seq, comb);

    // ===== final FC on tensor cores (TF32) =====
    gemm_tf32<<<gFC, 256, GEMM_SMEM>>>(comb, fcW, fcb, out, BB*TN, VV, H2);
}